// round 13
// baseline (speedup 1.0000x reference)
#include <cuda_runtime.h>
#include <cuda_fp16.h>
#include <cstdint>

// TinyTransformer on GB300 — round 13: attention S-MMA with fp16 accumulator
// (2x legacy-pipe rate; K=64 accumulation, error ~2.4e-4 in p, ~5e-6 in O).
// GEMM unchanged (occupancy/reg-ceiling bound at ~55% tensor).

#define TL   4
#define TT   1024
#define TB   4
#define TD   1024
#define TH   16
#define TFF  4096
#define NTOK 4096
#define KQVN 3072
#define EPSN 1e-6f

// GEMM tiling: BM=BN=128, BK=64 halves, 3-stage cp.async, 256 threads
#define BKT 64
#define NSTG 3
#define ROWB 144
#define TILE_BYTES (128 * ROWB)
#define STG_BYTES (2 * TILE_BYTES)
#define GSMEM (NSTG * STG_BYTES)        // 110592

// attention smem (bytes): K 128 rows; Q/V double-buffered 64 rows each
#define A_K  0
#define A_Q  18432      // + qb*9216
#define A_V  36864      // + qb*9216
#define ASMEM 55296

// ---------------- scratch ----------------
__device__ __half g_W1t [(size_t)TL * TFF * TD];
__device__ __half g_W2t [(size_t)TL * TD * TFF];
__device__ __half g_KQVt[(size_t)TL * KQVN * TD];
__device__ float  g_bkqv[(size_t)TL * KQVN];
__device__ __half g_Xh [(size_t)NTOK * TD];
__device__ __half g_Y1h[(size_t)NTOK * TFF];
__device__ float  g_F  [(size_t)NTOK * TD];
__device__ float  g_Z  [(size_t)NTOK * TD];
__device__ __half g_Zh [(size_t)NTOK * TD];
__device__ __half g_KQVh[(size_t)NTOK * KQVN];
__device__ float  g_Ob [(size_t)NTOK * TD];
__device__ float  g_Xb [(size_t)NTOK * TD];
__device__ __half g_Xbh[(size_t)NTOK * TD];

// ---------------- helpers ----------------
__device__ __forceinline__ uint32_t smem_u32(const void* p) {
    uint32_t a;
    asm("{ .reg .u64 t; cvta.to.shared.u64 t, %1; cvt.u32.u64 %0, t; }" : "=r"(a) : "l"(p));
    return a;
}
__device__ __forceinline__ void cp_async16(uint32_t dst, const void* src) {
    asm volatile("cp.async.cg.shared.global [%0], [%1], 16;" :: "r"(dst), "l"(src));
}
__device__ __forceinline__ void ldm4(uint32_t r[4], uint32_t addr) {
    asm volatile("ldmatrix.sync.aligned.m8n8.x4.shared.b16 {%0,%1,%2,%3}, [%4];"
                 : "=r"(r[0]), "=r"(r[1]), "=r"(r[2]), "=r"(r[3]) : "r"(addr));
}
__device__ __forceinline__ void ldm4t(uint32_t r[4], uint32_t addr) {
    asm volatile("ldmatrix.sync.aligned.m8n8.x4.trans.shared.b16 {%0,%1,%2,%3}, [%4];"
                 : "=r"(r[0]), "=r"(r[1]), "=r"(r[2]), "=r"(r[3]) : "r"(addr));
}
__device__ __forceinline__ void mma16(float d[4], const uint32_t a[4], const uint32_t b0,
                                      const uint32_t b1) {
    asm("mma.sync.aligned.m16n8k16.row.col.f32.f16.f16.f32 "
        "{%0,%1,%2,%3}, {%4,%5,%6,%7}, {%8,%9}, {%0,%1,%2,%3};"
        : "+f"(d[0]), "+f"(d[1]), "+f"(d[2]), "+f"(d[3])
        : "r"(a[0]), "r"(a[1]), "r"(a[2]), "r"(a[3]), "r"(b0), "r"(b1));
}
// fp16-accumulator variant (2x rate): D/C are 2x f16x2 regs {row g, row g+8}
__device__ __forceinline__ void mma16h(uint32_t d[2], const uint32_t a[4], const uint32_t b0,
                                       const uint32_t b1) {
    asm("mma.sync.aligned.m16n8k16.row.col.f16.f16.f16.f16 "
        "{%0,%1}, {%2,%3,%4,%5}, {%6,%7}, {%0,%1};"
        : "+r"(d[0]), "+r"(d[1])
        : "r"(a[0]), "r"(a[1]), "r"(a[2]), "r"(a[3]), "r"(b0), "r"(b1));
}
// pack {lo, hi} fp32 -> one b32 half2 register (cvt puts first operand in UPPER half)
__device__ __forceinline__ uint32_t h2pack(float lo, float hi) {
    uint32_t r;
    asm("cvt.rn.f16x2.f32 %0, %1, %2;" : "=r"(r) : "f"(hi), "f"(lo));
    return r;
}
__device__ __forceinline__ float2 h2unpack(uint32_t u) {
    __half2 h = *reinterpret_cast<__half2*>(&u);
    return __half22float2(h);
}

// ---------------- GEMM (unchanged) ----------------
template <bool RELU, bool OUTHALF>
__global__ void __launch_bounds__(256, 2)
gemm_h(const __half* __restrict__ A, const __half* __restrict__ Bt,
       const float* __restrict__ bias, void* __restrict__ Cv,
       int M, int N, int K)
{
    extern __shared__ __align__(128) char smem[];
    const uint32_t sb = smem_u32(smem);
    const int tid  = threadIdx.x;
    const int lane = tid & 31, warp = tid >> 5;
    const int g = lane >> 2, q4 = lane & 3;
    const int wm = warp >> 2, wn = warp & 3;
    const int bm = blockIdx.y << 7, bn = blockIdx.x << 7;
    const int S = K / BKT;

    const int ldRow = tid >> 3;
    const int ldColB = (tid & 7) << 4;
    const int ldColH = (tid & 7) << 3;

    auto load_stage = [&](int s) {
        const int buf = s - (s / NSTG) * NSTG;
        const uint32_t base = sb + buf * STG_BYTES;
        const int k0 = s * BKT;
        #pragma unroll
        for (int i = 0; i < 4; i++) {
            const int r = ldRow + (i << 5);
            cp_async16(base + r * ROWB + ldColB,
                       A + (size_t)(bm + r) * K + k0 + ldColH);
        }
        #pragma unroll
        for (int i = 0; i < 4; i++) {
            const int r = ldRow + (i << 5);
            cp_async16(base + TILE_BYTES + r * ROWB + ldColB,
                       Bt + (size_t)(bn + r) * K + k0 + ldColH);
        }
        asm volatile("cp.async.commit_group;");
    };

    load_stage(0);
    load_stage(1);

    float acc[4][4][4];
    #pragma unroll
    for (int i = 0; i < 4; i++)
        #pragma unroll
        for (int j = 0; j < 4; j++)
            #pragma unroll
            for (int k = 0; k < 4; k++) acc[i][j][k] = 0.f;

    const int aRow = (wm << 6) + (lane & 15);
    const int aByte = (lane >> 4) << 4;
    const int bRow = (wn << 5) + ((lane >> 4) << 3) + (lane & 7);
    const int bByte = ((lane >> 3) & 1) << 4;

    for (int s = 0; s < S; s++) {
        const int buf = s - (s / NSTG) * NSTG;
        asm volatile("cp.async.wait_group 1;");
        __syncthreads();
        if (s + 2 < S) load_stage(s + 2);
        else           asm volatile("cp.async.commit_group;");

        const uint32_t aBase = sb + buf * STG_BYTES;
        const uint32_t bBase = aBase + TILE_BYTES;

        #pragma unroll
        for (int ks = 0; ks < 4; ks++) {
            uint32_t af[4][4], bf[4][2];
            #pragma unroll
            for (int mt = 0; mt < 4; mt++)
                ldm4(af[mt], aBase + (aRow + (mt << 4)) * ROWB + (ks << 5) + aByte);
            #pragma unroll
            for (int p = 0; p < 2; p++) {
                uint32_t r[4];
                ldm4(r, bBase + (bRow + (p << 4)) * ROWB + (ks << 5) + bByte);
                bf[2 * p][0] = r[0]; bf[2 * p][1] = r[1];
                bf[2 * p + 1][0] = r[2]; bf[2 * p + 1][1] = r[3];
            }
            #pragma unroll
            for (int mt = 0; mt < 4; mt++)
                #pragma unroll
                for (int nt = 0; nt < 4; nt++)
                    mma16(acc[mt][nt], af[mt], bf[nt][0], bf[nt][1]);
        }
        __syncthreads();
    }

    #pragma unroll
    for (int mt = 0; mt < 4; mt++) {
        const int r = bm + (wm << 6) + (mt << 4) + g;
        #pragma unroll
        for (int nt = 0; nt < 4; nt++) {
            const int c = bn + (wn << 5) + (nt << 3) + (q4 << 1);
            const float b0 = bias[c], b1 = bias[c + 1];
            float v0 = acc[mt][nt][0] + b0, v1 = acc[mt][nt][1] + b1;
            float v2 = acc[mt][nt][2] + b0, v3 = acc[mt][nt][3] + b1;
            if (RELU) {
                v0 = fmaxf(v0, 0.f); v1 = fmaxf(v1, 0.f);
                v2 = fmaxf(v2, 0.f); v3 = fmaxf(v3, 0.f);
            }
            if (OUTHALF) {
                __half* Ch = (__half*)Cv;
                *(__half2*)(Ch + (size_t)r * N + c)       = __floats2half2_rn(v0, v1);
                *(__half2*)(Ch + (size_t)(r + 8) * N + c) = __floats2half2_rn(v2, v3);
            } else {
                float* Cf = (float*)Cv;
                *(float2*)(Cf + (size_t)r * N + c)       = make_float2(v0, v1);
                *(float2*)(Cf + (size_t)(r + 8) * N + c) = make_float2(v2, v3);
            }
        }
    }
}

// ---------------- merged weight prep ----------------
__global__ void transpose_all(const float* __restrict__ W1, const float* __restrict__ W2,
                              const float* __restrict__ Wk, const float* __restrict__ Wq,
                              const float* __restrict__ Wv,
                              __half* __restrict__ W1t, __half* __restrict__ W2t,
                              __half* __restrict__ KQVt)
{
    __shared__ float t[32][33];
    const int l = blockIdx.y;
    int id = blockIdx.x;
    const float* src; __half* dst; int R, Cc, ct, rt;
    if (id < 4096) {
        src = W1 + (size_t)l * TD * TFF; dst = W1t + (size_t)l * TFF * TD;
        R = TD; Cc = TFF; ct = id & 127; rt = id >> 7;
    } else if (id < 8192) {
        id -= 4096;
        src = W2 + (size_t)l * TFF * TD; dst = W2t + (size_t)l * TD * TFF;
        R = TFF; Cc = TD; ct = id & 31; rt = id >> 5;
    } else {
        id -= 8192;
        const int w = id >> 10; id &= 1023;
        src = (w == 0 ? Wk : w == 1 ? Wq : Wv) + (size_t)l * TD * TD;
        dst = KQVt + (size_t)l * KQVN * TD + (size_t)w * 1024 * TD;
        R = TD; Cc = TD; ct = id & 31; rt = id >> 5;
    }
    const int c0 = ct << 5, r0 = rt << 5;
    const int tx = threadIdx.x, ty = threadIdx.y;
    #pragma unroll
    for (int i = 0; i < 32; i += 8)
        t[ty + i][tx] = src[(size_t)(r0 + ty + i) * Cc + c0 + tx];
    __syncthreads();
    #pragma unroll
    for (int i = 0; i < 32; i += 8)
        dst[(size_t)(c0 + ty + i) * R + r0 + tx] = __float2half_rn(t[tx][ty + i]);
}

__global__ void pack_bias(const float* __restrict__ bk, const float* __restrict__ bq,
                          const float* __restrict__ bv, float* __restrict__ dst)
{
    const int l = blockIdx.y;
    const int j = (blockIdx.x << 8) + threadIdx.x;
    float v;
    if (j < 1024)      v = bk[l * 1024 + j];
    else if (j < 2048) v = bq[l * 1024 + j - 1024];
    else               v = bv[l * 1024 + j - 2048];
    dst[l * KQVN + j] = v;
}

__global__ void half_copy(const float* __restrict__ s, __half* __restrict__ d)
{
    const int i = (blockIdx.x << 8) + threadIdx.x;
    const float4 v = ((const float4*)s)[i];
    *(__half2*)(d + (size_t)i * 4)     = __floats2half2_rn(v.x, v.y);
    *(__half2*)(d + (size_t)i * 4 + 2) = __floats2half2_rn(v.z, v.w);
}

// ---------------- flash attention (query=K, key=Q, value=V) ----------------
// grid (TT/128, TB*TH); 256 threads = 8 warps, each 16 i-rows of a 128-row i-tile.
// S-MMA in fp16 accumulate (2x rate); O-MMA fp32 accumulate.
__global__ void __launch_bounds__(256, 2)
attn_h(const __half* __restrict__ Kh, const __half* __restrict__ Qh,
       const __half* __restrict__ Vh, float* __restrict__ Ob, int kst)
{
    extern __shared__ __align__(128) char smem[];
    const uint32_t sb = smem_u32(smem);
    const int tid  = threadIdx.x;
    const int lane = tid & 31, warp = tid >> 5;
    const int g = lane >> 2, q4 = lane & 3;
    const int b = blockIdx.y >> 4, h = blockIdx.y & 15;
    const int i0 = blockIdx.x << 7;
    const int cb = h << 6;
    const int iw = warp << 4;

    const int ldRow = tid >> 3;
    const int ldColB = (tid & 7) << 4;
    const int ldColH = (tid & 7) << 3;

    auto loadQV = [&](int j0, int qb) {
        #pragma unroll
        for (int i = 0; i < 2; i++) {
            const int r = ldRow + (i << 5);
            const size_t ga = (size_t)((j0 + r) * TB + b) * kst + cb + ldColH;
            cp_async16(sb + A_Q + qb * 9216 + r * ROWB + ldColB, Qh + ga);
            cp_async16(sb + A_V + qb * 9216 + r * ROWB + ldColB, Vh + ga);
        }
        asm volatile("cp.async.commit_group;");
    };

    loadQV(0, 0);

    // K tile: 128 rows (plain loads)
    #pragma unroll
    for (int i = 0; i < 4; i++) {
        const int r = ldRow + (i << 5);
        const size_t ga = (size_t)((i0 + r) * TB + b) * kst + cb + ldColH;
        const uint4 v = *(const uint4*)(Kh + ga);
        *(uint4*)(smem + A_K + r * ROWB + ldColB) = v;
    }
    __syncthreads();

    // hoist K fragments (loop-invariant A operand of S = K @ Q^T)
    const int aRow = iw + (lane & 15);
    const int aByte = (lane >> 4) << 4;
    uint32_t kf[4][4];
    #pragma unroll
    for (int ks = 0; ks < 4; ks++)
        ldm4(kf[ks], sb + A_K + aRow * ROWB + (ks << 5) + aByte);

    float l0 = 0.f, l1 = 0.f;
    float o[8][4];
    #pragma unroll
    for (int i = 0; i < 8; i++)
        #pragma unroll
        for (int j = 0; j < 4; j++) o[i][j] = 0.f;

    const int bRowQ = ((lane >> 4) << 3) + (lane & 7);
    const int bByteQ = ((lane >> 3) & 1) << 4;
    const int vRow = ((lane >> 3) & 1) * 8 + (lane & 7);
    const int vByte = (lane >> 4) << 4;

    for (int jt = 0; jt < 16; jt++) {
        const int qb = jt & 1;
        asm volatile("cp.async.wait_group 0;");
        __syncthreads();                 // Q/V[qb] ready; qb^1 readers (jt-1) done
        if (jt < 15) loadQV((jt + 1) << 6, qb ^ 1);

        const uint32_t qBase = sb + A_Q + qb * 9216;
        const uint32_t vBase = sb + A_V + qb * 9216;

        // S = K_i @ Q_j^T, fp16 accumulate: sh[nt] = {row g pair, row g+8 pair}
        uint32_t sh[8][2];
        #pragma unroll
        for (int i = 0; i < 8; i++) { sh[i][0] = 0u; sh[i][1] = 0u; }

        #pragma unroll
        for (int ks = 0; ks < 4; ks++) {
            #pragma unroll
            for (int pj = 0; pj < 4; pj++) {
                uint32_t r[4];
                ldm4(r, qBase + ((pj << 4) + bRowQ) * ROWB + (ks << 5) + bByteQ);
                mma16h(sh[2 * pj], kf[ks], r[0], r[1]);
                mma16h(sh[2 * pj + 1], kf[ks], r[2], r[3]);
            }
        }

        // exp (no max subtraction: scores tiny), accumulate row sums
        const float scale = 0.03125f;
        float p[8][4];
        float rs0 = 0.f, rs1 = 0.f;
        #pragma unroll
        for (int nt = 0; nt < 8; nt++) {
            const float2 v01 = h2unpack(sh[nt][0]);   // row g
            const float2 v23 = h2unpack(sh[nt][1]);   // row g+8
            p[nt][0] = __expf(v01.x * scale);
            p[nt][1] = __expf(v01.y * scale);
            p[nt][2] = __expf(v23.x * scale);
            p[nt][3] = __expf(v23.y * scale);
            rs0 += p[nt][0] + p[nt][1];
            rs1 += p[nt][2] + p[nt][3];
        }
        rs0 += __shfl_xor_sync(0xffffffffu, rs0, 1);
        rs0 += __shfl_xor_sync(0xffffffffu, rs0, 2);
        rs1 += __shfl_xor_sync(0xffffffffu, rs1, 1);
        rs1 += __shfl_xor_sync(0xffffffffu, rs1, 2);
        l0 += rs0;
        l1 += rs1;

        // O += P @ V (P packed from fp32 p, C-frag == A-frag layout)
        #pragma unroll
        for (int kc = 0; kc < 4; kc++) {
            uint32_t pf[4];
            pf[0] = h2pack(p[2 * kc][0],     p[2 * kc][1]);
            pf[1] = h2pack(p[2 * kc][2],     p[2 * kc][3]);
            pf[2] = h2pack(p[2 * kc + 1][0], p[2 * kc + 1][1]);
            pf[3] = h2pack(p[2 * kc + 1][2], p[2 * kc + 1][3]);
            #pragma unroll
            for (int dp = 0; dp < 4; dp++) {
                uint32_t r[4];
                ldm4t(r, vBase + ((kc << 4) + vRow) * ROWB + (dp << 5) + vByte);
                mma16(o[2 * dp], pf, r[0], r[1]);
                mma16(o[2 * dp + 1], pf, r[2], r[3]);
            }
        }
    }

    const float inv0 = 1.f / l0, inv1 = 1.f / l1;
    const size_t r0 = (size_t)((i0 + iw + g) * TB + b) * TD + cb;
    const size_t r1 = (size_t)((i0 + iw + 8 + g) * TB + b) * TD + cb;
    #pragma unroll
    for (int nt = 0; nt < 8; nt++) {
        const int c = (nt << 3) + (q4 << 1);
        *(float2*)(Ob + r0 + c) = make_float2(o[nt][0] * inv0, o[nt][1] * inv0);
        *(float2*)(Ob + r1 + c) = make_float2(o[nt][2] * inv1, o[nt][3] * inv1);
    }
}

// ---------------- resnorm ----------------
template <bool WRITEH>
__global__ void __launch_bounds__(256)
resnorm_k(const float* __restrict__ X, const float* __restrict__ Fx,
          float* __restrict__ Out, __half* __restrict__ OutH)
{
    __shared__ float sred[16];
    const int row = blockIdx.x, tid = threadIdx.x;
    const int lane = tid & 31, warp = tid >> 5;
    const size_t base = (size_t)row * TD + (tid << 2);

    const float4 xv = *(const float4*)(X + base);
    const float4 fv = *(const float4*)(Fx + base);
    const float y0 = xv.x + fv.x, y1 = xv.y + fv.y, y2 = xv.z + fv.z, y3 = xv.w + fv.w;

    float s = y0 + y1 + y2 + y3;
    float q = y0 * y0 + y1 * y1 + y2 * y2 + y3 * y3;
    #pragma unroll
    for (int o = 16; o; o >>= 1) {
        s += __shfl_xor_sync(0xffffffffu, s, o);
        q += __shfl_xor_sync(0xffffffffu, q, o);
    }
    if (lane == 0) { sred[warp] = s; sred[8 + warp] = q; }
    __syncthreads();
    if (tid == 0) {
        float ts = 0.f, tq = 0.f;
        #pragma unroll
        for (int i = 0; i < 8; i++) { ts += sred[i]; tq += sred[8 + i]; }
        const float mu = ts * (1.f / TD);
        float var = (tq - mu * ts) * (1.f / (TD - 1));
        var = fmaxf(var, 0.f);
        sred[0] = mu;
        sred[1] = 1.f / (sqrtf(var) + EPSN);
    }
    __syncthreads();
    const float mu = sred[0], inv = sred[1];
    const float v0 = (y0 - mu) * inv, v1 = (y1 - mu) * inv;
    const float v2 = (y2 - mu) * inv, v3 = (y3 - mu) * inv;
    *(float4*)(Out + base) = make_float4(v0, v1, v2, v3);
    if (WRITEH) {
        *(__half2*)(OutH + base)     = __floats2half2_rn(v0, v1);
        *(__half2*)(OutH + base + 2) = __floats2half2_rn(v2, v3);
    }
}

// ---------------- launch ----------------
extern "C" void kernel_launch(void* const* d_in, const int* in_sizes, int n_in,
                              void* d_out, int out_size)
{
    (void)in_sizes; (void)n_in; (void)out_size;
    const float* x  = (const float*)d_in[0];
    const float* Wk = (const float*)d_in[2];
    const float* bk = (const float*)d_in[3];
    const float* Wq = (const float*)d_in[4];
    const float* bq = (const float*)d_in[5];
    const float* Wv = (const float*)d_in[6];
    const float* bv = (const float*)d_in[7];
    const float* W1 = (const float*)d_in[8];
    const float* b1 = (const float*)d_in[9];
    const float* W2 = (const float*)d_in[10];
    const float* b2 = (const float*)d_in[11];

    __half *pW1t, *pW2t, *pKQVt, *pXh, *pY1h, *pZh, *pKQVh, *pXbh;
    float  *pbkqv, *pF, *pZ, *pO, *pX;
    cudaGetSymbolAddress((void**)&pW1t,  g_W1t);
    cudaGetSymbolAddress((void**)&pW2t,  g_W2t);
    cudaGetSymbolAddress((void**)&pKQVt, g_KQVt);
    cudaGetSymbolAddress((void**)&pbkqv, g_bkqv);
    cudaGetSymbolAddress((void**)&pXh,   g_Xh);
    cudaGetSymbolAddress((void**)&pY1h,  g_Y1h);
    cudaGetSymbolAddress((void**)&pF,    g_F);
    cudaGetSymbolAddress((void**)&pZ,    g_Z);
    cudaGetSymbolAddress((void**)&pZh,   g_Zh);
    cudaGetSymbolAddress((void**)&pKQVh, g_KQVh);
    cudaGetSymbolAddress((void**)&pO,    g_Ob);
    cudaGetSymbolAddress((void**)&pX,    g_Xb);
    cudaGetSymbolAddress((void**)&pXbh,  g_Xbh);

    cudaFuncSetAttribute(gemm_h<true, true>,   cudaFuncAttributeMaxDynamicSharedMemorySize, GSMEM);
    cudaFuncSetAttribute(gemm_h<true, false>,  cudaFuncAttributeMaxDynamicSharedMemorySize, GSMEM);
    cudaFuncSetAttribute(gemm_h<false, true>,  cudaFuncAttributeMaxDynamicSharedMemorySize, GSMEM);
    cudaFuncSetAttribute(attn_h, cudaFuncAttributeMaxDynamicSharedMemorySize, ASMEM);

    transpose_all<<<dim3(11264, TL), dim3(32, 8)>>>(W1, W2, Wk, Wq, Wv, pW1t, pW2t, pKQVt);
    half_copy<<<NTOK * TD / 4 / 256, 256>>>(x, pXh);
    pack_bias<<<dim3(KQVN / 256, TL), 256>>>(bk, bq, bv, pbkqv);

    const __half* curAh = pXh;
    const float*  curR  = x;

    for (int l = 0; l < TL; l++) {
        gemm_h<true, true><<<dim3(TFF / 128, NTOK / 128), 256, GSMEM>>>(
            curAh, pW1t + (size_t)l * TFF * TD, b1 + l * TFF, pY1h, NTOK, TFF, TD);
        gemm_h<true, false><<<dim3(TD / 128, NTOK / 128), 256, GSMEM>>>(
            pY1h, pW2t + (size_t)l * TD * TFF, b2 + l * TD, pF, NTOK, TD, TFF);
        resnorm_k<true><<<NTOK, 256>>>(curR, pF, pZ, pZh);

        gemm_h<false, true><<<dim3(KQVN / 128, NTOK / 128), 256, GSMEM>>>(
            pZh, pKQVt + (size_t)l * KQVN * TD, pbkqv + (size_t)l * KQVN, pKQVh, NTOK, KQVN, TD);

        attn_h<<<dim3(TT / 128, TB * TH), 256, ASMEM>>>(
            pKQVh, pKQVh + 1024, pKQVh + 2048, pO, KQVN);

        if (l == TL - 1) {
            resnorm_k<false><<<NTOK, 256>>>(pZ, pO, (float*)d_out, nullptr);
        } else {
            resnorm_k<true><<<NTOK, 256>>>(pZ, pO, pX, pXbh);
            curAh = pXbh;
            curR = pX;
        }
    }
}

// round 14
// speedup vs baseline: 1.0214x; 1.0214x over previous
#include <cuda_runtime.h>
#include <cuda_fp16.h>
#include <cstdint>

// TinyTransformer on GB300 — round 14: attention MUFU fix.
// ex2.approx.f16x2 (2 exps / MUFU op), scale*log2e folded into K fragments,
// P = ex2 output used directly as A-frags, l-reduction shfls deferred.
// GEMM unchanged.

#define TL   4
#define TT   1024
#define TB   4
#define TD   1024
#define TH   16
#define TFF  4096
#define NTOK 4096
#define KQVN 3072
#define EPSN 1e-6f

// GEMM tiling: BM=BN=128, BK=64 halves, 3-stage cp.async, 256 threads
#define BKT 64
#define NSTG 3
#define ROWB 144
#define TILE_BYTES (128 * ROWB)
#define STG_BYTES (2 * TILE_BYTES)
#define GSMEM (NSTG * STG_BYTES)        // 110592

// attention smem (bytes): K 128 rows; Q/V double-buffered 64 rows each
#define A_K  0
#define A_Q  18432      // + qb*9216
#define A_V  36864      // + qb*9216
#define ASMEM 55296

// ---------------- scratch ----------------
__device__ __half g_W1t [(size_t)TL * TFF * TD];
__device__ __half g_W2t [(size_t)TL * TD * TFF];
__device__ __half g_KQVt[(size_t)TL * KQVN * TD];
__device__ float  g_bkqv[(size_t)TL * KQVN];
__device__ __half g_Xh [(size_t)NTOK * TD];
__device__ __half g_Y1h[(size_t)NTOK * TFF];
__device__ float  g_F  [(size_t)NTOK * TD];
__device__ float  g_Z  [(size_t)NTOK * TD];
__device__ __half g_Zh [(size_t)NTOK * TD];
__device__ __half g_KQVh[(size_t)NTOK * KQVN];
__device__ float  g_Ob [(size_t)NTOK * TD];
__device__ float  g_Xb [(size_t)NTOK * TD];
__device__ __half g_Xbh[(size_t)NTOK * TD];

// ---------------- helpers ----------------
__device__ __forceinline__ uint32_t smem_u32(const void* p) {
    uint32_t a;
    asm("{ .reg .u64 t; cvta.to.shared.u64 t, %1; cvt.u32.u64 %0, t; }" : "=r"(a) : "l"(p));
    return a;
}
__device__ __forceinline__ void cp_async16(uint32_t dst, const void* src) {
    asm volatile("cp.async.cg.shared.global [%0], [%1], 16;" :: "r"(dst), "l"(src));
}
__device__ __forceinline__ void ldm4(uint32_t r[4], uint32_t addr) {
    asm volatile("ldmatrix.sync.aligned.m8n8.x4.shared.b16 {%0,%1,%2,%3}, [%4];"
                 : "=r"(r[0]), "=r"(r[1]), "=r"(r[2]), "=r"(r[3]) : "r"(addr));
}
__device__ __forceinline__ void ldm4t(uint32_t r[4], uint32_t addr) {
    asm volatile("ldmatrix.sync.aligned.m8n8.x4.trans.shared.b16 {%0,%1,%2,%3}, [%4];"
                 : "=r"(r[0]), "=r"(r[1]), "=r"(r[2]), "=r"(r[3]) : "r"(addr));
}
__device__ __forceinline__ void mma16(float d[4], const uint32_t a[4], const uint32_t b0,
                                      const uint32_t b1) {
    asm("mma.sync.aligned.m16n8k16.row.col.f32.f16.f16.f32 "
        "{%0,%1,%2,%3}, {%4,%5,%6,%7}, {%8,%9}, {%0,%1,%2,%3};"
        : "+f"(d[0]), "+f"(d[1]), "+f"(d[2]), "+f"(d[3])
        : "r"(a[0]), "r"(a[1]), "r"(a[2]), "r"(a[3]), "r"(b0), "r"(b1));
}
// fp16-accumulator variant (2x rate): D/C are 2x f16x2 regs {row g, row g+8}
__device__ __forceinline__ void mma16h(uint32_t d[2], const uint32_t a[4], const uint32_t b0,
                                       const uint32_t b1) {
    asm("mma.sync.aligned.m16n8k16.row.col.f16.f16.f16.f16 "
        "{%0,%1}, {%2,%3,%4,%5}, {%6,%7}, {%0,%1};"
        : "+r"(d[0]), "+r"(d[1])
        : "r"(a[0]), "r"(a[1]), "r"(a[2]), "r"(a[3]), "r"(b0), "r"(b1));
}
__device__ __forceinline__ uint32_t hmul2u(uint32_t a, uint32_t b) {
    uint32_t r;
    asm("mul.rn.f16x2 %0, %1, %2;" : "=r"(r) : "r"(a), "r"(b));
    return r;
}
__device__ __forceinline__ uint32_t hadd2u(uint32_t a, uint32_t b) {
    uint32_t r;
    asm("add.rn.f16x2 %0, %1, %2;" : "=r"(r) : "r"(a), "r"(b));
    return r;
}
__device__ __forceinline__ uint32_t ex2h2(uint32_t a) {
    uint32_t r;
    asm("ex2.approx.f16x2 %0, %1;" : "=r"(r) : "r"(a));
    return r;
}
__device__ __forceinline__ float2 h2unpack(uint32_t u) {
    __half2 h = *reinterpret_cast<__half2*>(&u);
    return __half22float2(h);
}

// ---------------- GEMM (unchanged) ----------------
template <bool RELU, bool OUTHALF>
__global__ void __launch_bounds__(256, 2)
gemm_h(const __half* __restrict__ A, const __half* __restrict__ Bt,
       const float* __restrict__ bias, void* __restrict__ Cv,
       int M, int N, int K)
{
    extern __shared__ __align__(128) char smem[];
    const uint32_t sb = smem_u32(smem);
    const int tid  = threadIdx.x;
    const int lane = tid & 31, warp = tid >> 5;
    const int g = lane >> 2, q4 = lane & 3;
    const int wm = warp >> 2, wn = warp & 3;
    const int bm = blockIdx.y << 7, bn = blockIdx.x << 7;
    const int S = K / BKT;

    const int ldRow = tid >> 3;
    const int ldColB = (tid & 7) << 4;
    const int ldColH = (tid & 7) << 3;

    auto load_stage = [&](int s) {
        const int buf = s - (s / NSTG) * NSTG;
        const uint32_t base = sb + buf * STG_BYTES;
        const int k0 = s * BKT;
        #pragma unroll
        for (int i = 0; i < 4; i++) {
            const int r = ldRow + (i << 5);
            cp_async16(base + r * ROWB + ldColB,
                       A + (size_t)(bm + r) * K + k0 + ldColH);
        }
        #pragma unroll
        for (int i = 0; i < 4; i++) {
            const int r = ldRow + (i << 5);
            cp_async16(base + TILE_BYTES + r * ROWB + ldColB,
                       Bt + (size_t)(bn + r) * K + k0 + ldColH);
        }
        asm volatile("cp.async.commit_group;");
    };

    load_stage(0);
    load_stage(1);

    float acc[4][4][4];
    #pragma unroll
    for (int i = 0; i < 4; i++)
        #pragma unroll
        for (int j = 0; j < 4; j++)
            #pragma unroll
            for (int k = 0; k < 4; k++) acc[i][j][k] = 0.f;

    const int aRow = (wm << 6) + (lane & 15);
    const int aByte = (lane >> 4) << 4;
    const int bRow = (wn << 5) + ((lane >> 4) << 3) + (lane & 7);
    const int bByte = ((lane >> 3) & 1) << 4;

    for (int s = 0; s < S; s++) {
        const int buf = s - (s / NSTG) * NSTG;
        asm volatile("cp.async.wait_group 1;");
        __syncthreads();
        if (s + 2 < S) load_stage(s + 2);
        else           asm volatile("cp.async.commit_group;");

        const uint32_t aBase = sb + buf * STG_BYTES;
        const uint32_t bBase = aBase + TILE_BYTES;

        #pragma unroll
        for (int ks = 0; ks < 4; ks++) {
            uint32_t af[4][4], bf[4][2];
            #pragma unroll
            for (int mt = 0; mt < 4; mt++)
                ldm4(af[mt], aBase + (aRow + (mt << 4)) * ROWB + (ks << 5) + aByte);
            #pragma unroll
            for (int p = 0; p < 2; p++) {
                uint32_t r[4];
                ldm4(r, bBase + (bRow + (p << 4)) * ROWB + (ks << 5) + bByte);
                bf[2 * p][0] = r[0]; bf[2 * p][1] = r[1];
                bf[2 * p + 1][0] = r[2]; bf[2 * p + 1][1] = r[3];
            }
            #pragma unroll
            for (int mt = 0; mt < 4; mt++)
                #pragma unroll
                for (int nt = 0; nt < 4; nt++)
                    mma16(acc[mt][nt], af[mt], bf[nt][0], bf[nt][1]);
        }
        __syncthreads();
    }

    #pragma unroll
    for (int mt = 0; mt < 4; mt++) {
        const int r = bm + (wm << 6) + (mt << 4) + g;
        #pragma unroll
        for (int nt = 0; nt < 4; nt++) {
            const int c = bn + (wn << 5) + (nt << 3) + (q4 << 1);
            const float b0 = bias[c], b1 = bias[c + 1];
            float v0 = acc[mt][nt][0] + b0, v1 = acc[mt][nt][1] + b1;
            float v2 = acc[mt][nt][2] + b0, v3 = acc[mt][nt][3] + b1;
            if (RELU) {
                v0 = fmaxf(v0, 0.f); v1 = fmaxf(v1, 0.f);
                v2 = fmaxf(v2, 0.f); v3 = fmaxf(v3, 0.f);
            }
            if (OUTHALF) {
                __half* Ch = (__half*)Cv;
                *(__half2*)(Ch + (size_t)r * N + c)       = __floats2half2_rn(v0, v1);
                *(__half2*)(Ch + (size_t)(r + 8) * N + c) = __floats2half2_rn(v2, v3);
            } else {
                float* Cf = (float*)Cv;
                *(float2*)(Cf + (size_t)r * N + c)       = make_float2(v0, v1);
                *(float2*)(Cf + (size_t)(r + 8) * N + c) = make_float2(v2, v3);
            }
        }
    }
}

// ---------------- merged weight prep ----------------
__global__ void transpose_all(const float* __restrict__ W1, const float* __restrict__ W2,
                              const float* __restrict__ Wk, const float* __restrict__ Wq,
                              const float* __restrict__ Wv,
                              __half* __restrict__ W1t, __half* __restrict__ W2t,
                              __half* __restrict__ KQVt)
{
    __shared__ float t[32][33];
    const int l = blockIdx.y;
    int id = blockIdx.x;
    const float* src; __half* dst; int R, Cc, ct, rt;
    if (id < 4096) {
        src = W1 + (size_t)l * TD * TFF; dst = W1t + (size_t)l * TFF * TD;
        R = TD; Cc = TFF; ct = id & 127; rt = id >> 7;
    } else if (id < 8192) {
        id -= 4096;
        src = W2 + (size_t)l * TFF * TD; dst = W2t + (size_t)l * TD * TFF;
        R = TFF; Cc = TD; ct = id & 31; rt = id >> 5;
    } else {
        id -= 8192;
        const int w = id >> 10; id &= 1023;
        src = (w == 0 ? Wk : w == 1 ? Wq : Wv) + (size_t)l * TD * TD;
        dst = KQVt + (size_t)l * KQVN * TD + (size_t)w * 1024 * TD;
        R = TD; Cc = TD; ct = id & 31; rt = id >> 5;
    }
    const int c0 = ct << 5, r0 = rt << 5;
    const int tx = threadIdx.x, ty = threadIdx.y;
    #pragma unroll
    for (int i = 0; i < 32; i += 8)
        t[ty + i][tx] = src[(size_t)(r0 + ty + i) * Cc + c0 + tx];
    __syncthreads();
    #pragma unroll
    for (int i = 0; i < 32; i += 8)
        dst[(size_t)(c0 + ty + i) * R + r0 + tx] = __float2half_rn(t[tx][ty + i]);
}

__global__ void pack_bias(const float* __restrict__ bk, const float* __restrict__ bq,
                          const float* __restrict__ bv, float* __restrict__ dst)
{
    const int l = blockIdx.y;
    const int j = (blockIdx.x << 8) + threadIdx.x;
    float v;
    if (j < 1024)      v = bk[l * 1024 + j];
    else if (j < 2048) v = bq[l * 1024 + j - 1024];
    else               v = bv[l * 1024 + j - 2048];
    dst[l * KQVN + j] = v;
}

__global__ void half_copy(const float* __restrict__ s, __half* __restrict__ d)
{
    const int i = (blockIdx.x << 8) + threadIdx.x;
    const float4 v = ((const float4*)s)[i];
    *(__half2*)(d + (size_t)i * 4)     = __floats2half2_rn(v.x, v.y);
    *(__half2*)(d + (size_t)i * 4 + 2) = __floats2half2_rn(v.z, v.w);
}

// ---------------- flash attention (query=K, key=Q, value=V) ----------------
// grid (TT/128, TB*TH); 256 threads = 8 warps, each 16 i-rows of a 128-row i-tile.
// S-MMA fp16 acc with scale*log2e folded into K; p = ex2.approx.f16x2 directly.
__global__ void __launch_bounds__(256, 2)
attn_h(const __half* __restrict__ Kh, const __half* __restrict__ Qh,
       const __half* __restrict__ Vh, float* __restrict__ Ob, int kst)
{
    extern __shared__ __align__(128) char smem[];
    const uint32_t sb = smem_u32(smem);
    const int tid  = threadIdx.x;
    const int lane = tid & 31, warp = tid >> 5;
    const int g = lane >> 2, q4 = lane & 3;
    const int b = blockIdx.y >> 4, h = blockIdx.y & 15;
    const int i0 = blockIdx.x << 7;
    const int cb = h << 6;
    const int iw = warp << 4;

    const int ldRow = tid >> 3;
    const int ldColB = (tid & 7) << 4;
    const int ldColH = (tid & 7) << 3;

    auto loadQV = [&](int j0, int qb) {
        #pragma unroll
        for (int i = 0; i < 2; i++) {
            const int r = ldRow + (i << 5);
            const size_t ga = (size_t)((j0 + r) * TB + b) * kst + cb + ldColH;
            cp_async16(sb + A_Q + qb * 9216 + r * ROWB + ldColB, Qh + ga);
            cp_async16(sb + A_V + qb * 9216 + r * ROWB + ldColB, Vh + ga);
        }
        asm volatile("cp.async.commit_group;");
    };

    loadQV(0, 0);

    // K tile: 128 rows (plain loads)
    #pragma unroll
    for (int i = 0; i < 4; i++) {
        const int r = ldRow + (i << 5);
        const size_t ga = (size_t)((i0 + r) * TB + b) * kst + cb + ldColH;
        const uint4 v = *(const uint4*)(Kh + ga);
        *(uint4*)(smem + A_K + r * ROWB + ldColB) = v;
    }
    __syncthreads();

    // hoist K fragments and fold in scale*log2(e) = (1/32)*1.44269504
    const int aRow = iw + (lane & 15);
    const int aByte = (lane >> 4) << 4;
    const __half2 schh = __float2half2_rn(0.03125f * 1.44269504f);
    const uint32_t sc2 = *reinterpret_cast<const uint32_t*>(&schh);
    uint32_t kf[4][4];
    #pragma unroll
    for (int ks = 0; ks < 4; ks++) {
        ldm4(kf[ks], sb + A_K + aRow * ROWB + (ks << 5) + aByte);
        #pragma unroll
        for (int i = 0; i < 4; i++) kf[ks][i] = hmul2u(kf[ks][i], sc2);
    }

    float l0 = 0.f, l1 = 0.f;
    float o[8][4];
    #pragma unroll
    for (int i = 0; i < 8; i++)
        #pragma unroll
        for (int j = 0; j < 4; j++) o[i][j] = 0.f;

    const int bRowQ = ((lane >> 4) << 3) + (lane & 7);
    const int bByteQ = ((lane >> 3) & 1) << 4;
    const int vRow = ((lane >> 3) & 1) * 8 + (lane & 7);
    const int vByte = (lane >> 4) << 4;

    for (int jt = 0; jt < 16; jt++) {
        const int qb = jt & 1;
        asm volatile("cp.async.wait_group 0;");
        __syncthreads();                 // Q/V[qb] ready; qb^1 readers (jt-1) done
        if (jt < 15) loadQV((jt + 1) << 6, qb ^ 1);

        const uint32_t qBase = sb + A_Q + qb * 9216;
        const uint32_t vBase = sb + A_V + qb * 9216;

        // Sh = (scale*log2e*K) @ Q^T, fp16 acc: sh[nt] = {row g pair, row g+8 pair}
        uint32_t sh[8][2];
        #pragma unroll
        for (int i = 0; i < 8; i++) { sh[i][0] = 0u; sh[i][1] = 0u; }

        #pragma unroll
        for (int ks = 0; ks < 4; ks++) {
            #pragma unroll
            for (int pj = 0; pj < 4; pj++) {
                uint32_t r[4];
                ldm4(r, qBase + ((pj << 4) + bRowQ) * ROWB + (ks << 5) + bByteQ);
                mma16h(sh[2 * pj], kf[ks], r[0], r[1]);
                mma16h(sh[2 * pj + 1], kf[ks], r[2], r[3]);
            }
        }

        // p = 2^sh (packed half2), row sums via hadd2 tree (shfl deferred to end)
        uint32_t ph[8][2];
        #pragma unroll
        for (int nt = 0; nt < 8; nt++) {
            ph[nt][0] = ex2h2(sh[nt][0]);
            ph[nt][1] = ex2h2(sh[nt][1]);
        }
        uint32_t a0 = hadd2u(ph[0][0], ph[1][0]);
        uint32_t a1 = hadd2u(ph[2][0], ph[3][0]);
        uint32_t a2 = hadd2u(ph[4][0], ph[5][0]);
        uint32_t a3 = hadd2u(ph[6][0], ph[7][0]);
        uint32_t b0r = hadd2u(ph[0][1], ph[1][1]);
        uint32_t b1r = hadd2u(ph[2][1], ph[3][1]);
        uint32_t b2r = hadd2u(ph[4][1], ph[5][1]);
        uint32_t b3r = hadd2u(ph[6][1], ph[7][1]);
        const float2 f0 = h2unpack(hadd2u(hadd2u(a0, a1), hadd2u(a2, a3)));
        const float2 f1 = h2unpack(hadd2u(hadd2u(b0r, b1r), hadd2u(b2r, b3r)));
        l0 += f0.x + f0.y;
        l1 += f1.x + f1.y;

        // O += P @ V (ph used directly as A-fragments)
        #pragma unroll
        for (int kc = 0; kc < 4; kc++) {
            uint32_t pf[4];
            pf[0] = ph[2 * kc][0];
            pf[1] = ph[2 * kc][1];
            pf[2] = ph[2 * kc + 1][0];
            pf[3] = ph[2 * kc + 1][1];
            #pragma unroll
            for (int dp = 0; dp < 4; dp++) {
                uint32_t r[4];
                ldm4t(r, vBase + ((kc << 4) + vRow) * ROWB + (dp << 5) + vByte);
                mma16(o[2 * dp], pf, r[0], r[1]);
                mma16(o[2 * dp + 1], pf, r[2], r[3]);
            }
        }
    }

    // deferred row-sum reduction across the q4 lane group
    l0 += __shfl_xor_sync(0xffffffffu, l0, 1);
    l0 += __shfl_xor_sync(0xffffffffu, l0, 2);
    l1 += __shfl_xor_sync(0xffffffffu, l1, 1);
    l1 += __shfl_xor_sync(0xffffffffu, l1, 2);

    const float inv0 = 1.f / l0, inv1 = 1.f / l1;
    const size_t r0 = (size_t)((i0 + iw + g) * TB + b) * TD + cb;
    const size_t r1 = (size_t)((i0 + iw + 8 + g) * TB + b) * TD + cb;
    #pragma unroll
    for (int nt = 0; nt < 8; nt++) {
        const int c = (nt << 3) + (q4 << 1);
        *(float2*)(Ob + r0 + c) = make_float2(o[nt][0] * inv0, o[nt][1] * inv0);
        *(float2*)(Ob + r1 + c) = make_float2(o[nt][2] * inv1, o[nt][3] * inv1);
    }
}

// ---------------- resnorm ----------------
template <bool WRITEH>
__global__ void __launch_bounds__(256)
resnorm_k(const float* __restrict__ X, const float* __restrict__ Fx,
          float* __restrict__ Out, __half* __restrict__ OutH)
{
    __shared__ float sred[16];
    const int row = blockIdx.x, tid = threadIdx.x;
    const int lane = tid & 31, warp = tid >> 5;
    const size_t base = (size_t)row * TD + (tid << 2);

    const float4 xv = *(const float4*)(X + base);
    const float4 fv = *(const float4*)(Fx + base);
    const float y0 = xv.x + fv.x, y1 = xv.y + fv.y, y2 = xv.z + fv.z, y3 = xv.w + fv.w;

    float s = y0 + y1 + y2 + y3;
    float q = y0 * y0 + y1 * y1 + y2 * y2 + y3 * y3;
    #pragma unroll
    for (int o = 16; o; o >>= 1) {
        s += __shfl_xor_sync(0xffffffffu, s, o);
        q += __shfl_xor_sync(0xffffffffu, q, o);
    }
    if (lane == 0) { sred[warp] = s; sred[8 + warp] = q; }
    __syncthreads();
    if (tid == 0) {
        float ts = 0.f, tq = 0.f;
        #pragma unroll
        for (int i = 0; i < 8; i++) { ts += sred[i]; tq += sred[8 + i]; }
        const float mu = ts * (1.f / TD);
        float var = (tq - mu * ts) * (1.f / (TD - 1));
        var = fmaxf(var, 0.f);
        sred[0] = mu;
        sred[1] = 1.f / (sqrtf(var) + EPSN);
    }
    __syncthreads();
    const float mu = sred[0], inv = sred[1];
    const float v0 = (y0 - mu) * inv, v1 = (y1 - mu) * inv;
    const float v2 = (y2 - mu) * inv, v3 = (y3 - mu) * inv;
    *(float4*)(Out + base) = make_float4(v0, v1, v2, v3);
    if (WRITEH) {
        *(__half2*)(OutH + base)     = __floats2half2_rn(v0, v1);
        *(__half2*)(OutH + base + 2) = __floats2half2_rn(v2, v3);
    }
}

// ---------------- launch ----------------
extern "C" void kernel_launch(void* const* d_in, const int* in_sizes, int n_in,
                              void* d_out, int out_size)
{
    (void)in_sizes; (void)n_in; (void)out_size;
    const float* x  = (const float*)d_in[0];
    const float* Wk = (const float*)d_in[2];
    const float* bk = (const float*)d_in[3];
    const float* Wq = (const float*)d_in[4];
    const float* bq = (const float*)d_in[5];
    const float* Wv = (const float*)d_in[6];
    const float* bv = (const float*)d_in[7];
    const float* W1 = (const float*)d_in[8];
    const float* b1 = (const float*)d_in[9];
    const float* W2 = (const float*)d_in[10];
    const float* b2 = (const float*)d_in[11];

    __half *pW1t, *pW2t, *pKQVt, *pXh, *pY1h, *pZh, *pKQVh, *pXbh;
    float  *pbkqv, *pF, *pZ, *pO, *pX;
    cudaGetSymbolAddress((void**)&pW1t,  g_W1t);
    cudaGetSymbolAddress((void**)&pW2t,  g_W2t);
    cudaGetSymbolAddress((void**)&pKQVt, g_KQVt);
    cudaGetSymbolAddress((void**)&pbkqv, g_bkqv);
    cudaGetSymbolAddress((void**)&pXh,   g_Xh);
    cudaGetSymbolAddress((void**)&pY1h,  g_Y1h);
    cudaGetSymbolAddress((void**)&pF,    g_F);
    cudaGetSymbolAddress((void**)&pZ,    g_Z);
    cudaGetSymbolAddress((void**)&pZh,   g_Zh);
    cudaGetSymbolAddress((void**)&pKQVh, g_KQVh);
    cudaGetSymbolAddress((void**)&pO,    g_Ob);
    cudaGetSymbolAddress((void**)&pX,    g_Xb);
    cudaGetSymbolAddress((void**)&pXbh,  g_Xbh);

    cudaFuncSetAttribute(gemm_h<true, true>,   cudaFuncAttributeMaxDynamicSharedMemorySize, GSMEM);
    cudaFuncSetAttribute(gemm_h<true, false>,  cudaFuncAttributeMaxDynamicSharedMemorySize, GSMEM);
    cudaFuncSetAttribute(gemm_h<false, true>,  cudaFuncAttributeMaxDynamicSharedMemorySize, GSMEM);
    cudaFuncSetAttribute(attn_h, cudaFuncAttributeMaxDynamicSharedMemorySize, ASMEM);

    transpose_all<<<dim3(11264, TL), dim3(32, 8)>>>(W1, W2, Wk, Wq, Wv, pW1t, pW2t, pKQVt);
    half_copy<<<NTOK * TD / 4 / 256, 256>>>(x, pXh);
    pack_bias<<<dim3(KQVN / 256, TL), 256>>>(bk, bq, bv, pbkqv);

    const __half* curAh = pXh;
    const float*  curR  = x;

    for (int l = 0; l < TL; l++) {
        gemm_h<true, true><<<dim3(TFF / 128, NTOK / 128), 256, GSMEM>>>(
            curAh, pW1t + (size_t)l * TFF * TD, b1 + l * TFF, pY1h, NTOK, TFF, TD);
        gemm_h<true, false><<<dim3(TD / 128, NTOK / 128), 256, GSMEM>>>(
            pY1h, pW2t + (size_t)l * TD * TFF, b2 + l * TD, pF, NTOK, TD, TFF);
        resnorm_k<true><<<NTOK, 256>>>(curR, pF, pZ, pZh);

        gemm_h<false, true><<<dim3(KQVN / 128, NTOK / 128), 256, GSMEM>>>(
            pZh, pKQVt + (size_t)l * KQVN * TD, pbkqv + (size_t)l * KQVN, pKQVh, NTOK, KQVN, TD);

        attn_h<<<dim3(TT / 128, TB * TH), 256, ASMEM>>>(
            pKQVh, pKQVh + 1024, pKQVh + 2048, pO, KQVN);

        if (l == TL - 1) {
            resnorm_k<false><<<NTOK, 256>>>(pZ, pO, (float*)d_out, nullptr);
        } else {
            resnorm_k<true><<<NTOK, 256>>>(pZ, pO, pX, pXbh);
            curAh = pXbh;
            curR = pX;
        }
    }
}